// round 15
// baseline (speedup 1.0000x reference)
#include <cuda_runtime.h>

// FWHT, DIM=4096, fp32, scale 1/64. Persistent grid-stride kernel:
// 592 CTAs (4 per SM on 148 SMs), each CTA loops over ~27 rows with the
// NEXT row's global loads issued immediately after the current row's data
// lands in smem -> loads are in flight under pass-2/3 compute, and the
// launch has no wave transitions (the suspected source of chip-wide DRAM
// request bubbles at grid=16384 / ~22 waves).
//
// Per row: three in-register H16 passes over bit groups {b0,b1,b10,b11} /
// {b2..b5} / {b6..b9}, two smem exchanges. 768 L1 wavefronts/row (minimum).
// I/O fully coalesced (4x LDG.128 lane-contiguous, 16x STG.32 warp-contiguous).
//
// Smem: 4096 words (16 KB). GF(2) swizzle P(e) = e ^ (b6<<2) ^ (b10<<3) ^ (b11<<4)
// -> bank bits (b0, b1, b2^b6, b3^b10, b4^b11). Verified conflict-free:
//   W1 STS.128: 8-lane phases vary b2b3b4 -> distinct 4-bank groups
//   P2 scalar:  lanes vary b0,b1,b6,b10,b11 -> bank bijective
//   P3 scalar:  lanes vary b0..b4 -> bank bijective
// Exchange 1 is warp-local (chunk bits 5..7 equal the warp id for both the
// W1 writes and the pass-2 reads) -> __syncwarp; exchange 2 crosses the CTA;
// end-of-iteration __syncthreads protects smem reuse across rows.

#define FWHT_DIM 4096
#define GRID_CTAS 592   // 4 * 148

__device__ __forceinline__ void h16(float (&v)[16]) {
#pragma unroll
    for (int h = 1; h < 16; h <<= 1) {
#pragma unroll
        for (int i = 0; i < 16; i++) {
            if (!(i & h)) {
                float a = v[i];
                float b = v[i + h];
                v[i]     = a + b;
                v[i + h] = a - b;
            }
        }
    }
}

__global__ __launch_bounds__(256)
void fwht4096_kernel(const float* __restrict__ x, float* __restrict__ y,
                     int rows) {
    __shared__ float s[4096];   // 16 KB, swizzled; reused every row

    const int t = threadIdx.x;                    // 0..255
    const int stride = gridDim.x;

    // Precomputed per-thread constants (loop-invariant).
    const int tb   = t ^ ((t >> 4) & 1);          // W1 chunk swizzle base
    const int base = ((t >> 1) & 3) | ((t & 1) << 6) | ((t >> 5) << 7)
                   | (((t >> 3) & 3) << 10);      // pass-2 base
    const int sw   = ((t & 1) << 2) | (((t >> 3) & 1) << 3)
                   | (((t >> 4) & 1) << 4);       // pass-2 swizzle
    const int basew = (t & 63) | ((t >> 6) << 10);            // pass-3 base
    const int pb    = basew ^ ((((t >> 6) & 1) << 3) | (((t >> 7) & 1) << 4));
    const float sc = 0.015625f;                   // 1/64 = 1/sqrt(4096)

    int r = blockIdx.x;
    if (r >= rows) return;

    // Prologue: prefetch first row.
    float4 f[4];
    {
        const float4* __restrict__ p =
            reinterpret_cast<const float4*>(x + (size_t)r * FWHT_DIM);
#pragma unroll
        for (int j = 0; j < 4; j++) f[j] = __ldcs(p + t + 256 * j);
    }

    for (; r < rows; r += stride) {
        float v[16];
#pragma unroll
        for (int j = 0; j < 4; j++) {
            v[4 * j + 0] = f[j].x; v[4 * j + 1] = f[j].y;
            v[4 * j + 2] = f[j].z; v[4 * j + 3] = f[j].w;
        }

        h16(v);   // H16 over {b0,b1,b10,b11}

        // W1: 4x STS.128, swizzled chunk index (flips c0^=b6, c1^=b10, c2^=b11)
        {
            float4* s4 = reinterpret_cast<float4*>(s);
#pragma unroll
            for (int j = 0; j < 4; j++) {
                int cj = (tb ^ ((j & 1) << 1) ^ ((j & 2) << 1)) + 256 * j;
                s4[cj] = make_float4(v[4 * j], v[4 * j + 1],
                                     v[4 * j + 2], v[4 * j + 3]);
            }
        }
        __syncwarp();   // exchange 1 is warp-local by construction

        // Prefetch NEXT row now: v regs' data is safe in smem, f regs are free.
        // These 4 LDG.128 stay in flight under pass-2/3 compute.
        const int rn = r + stride;
        if (rn < rows) {
            const float4* __restrict__ pn =
                reinterpret_cast<const float4*>(x + (size_t)rn * FWHT_DIM);
#pragma unroll
            for (int j = 0; j < 4; j++) f[j] = __ldcs(pn + t + 256 * j);
        }

        // Pass 2: thread owns b6=t&1, b0b1=(t>>1)&3, b10b11=(t>>3)&3, b7b8b9=t>>5
#pragma unroll
        for (int m = 0; m < 16; m++)
            v[m] = s[base + ((4 * m) ^ sw)];

        h16(v);   // H16 over {b2..b5}

#pragma unroll
        for (int m = 0; m < 16; m++)
            s[base + ((4 * m) ^ sw)] = v[m];

        __syncthreads();   // exchange 2 crosses the whole CTA

        // Pass 3: thread owns b0..b5 = t&63, b10b11 = t>>6; regs k = b6..b9
#pragma unroll
        for (int k = 0; k < 16; k++)
            v[k] = s[(pb + 64 * k) ^ ((k & 1) << 2)];

        h16(v);   // H16 over {b6..b9}

        float* __restrict__ yr = y + (size_t)r * FWHT_DIM + basew;
#pragma unroll
        for (int k = 0; k < 16; k++)
            __stcs(yr + 64 * k, v[k] * sc);   // warp-contiguous, 1 wf each

        __syncthreads();   // smem safe to overwrite next iteration
    }
}

extern "C" void kernel_launch(void* const* d_in, const int* in_sizes, int n_in,
                              void* d_out, int out_size) {
    (void)n_in; (void)out_size;
    const float* x = (const float*)d_in[0];
    float* y = (float*)d_out;
    const int rows = in_sizes[0] / FWHT_DIM;   // 16384
    const int grid = rows < GRID_CTAS ? rows : GRID_CTAS;
    fwht4096_kernel<<<grid, 256>>>(x, y, rows);
}

// round 16
// speedup vs baseline: 1.1804x; 1.1804x over previous
#include <cuda_runtime.h>

// FWHT, DIM=4096, fp32, scale 1/64. Three in-register H16 passes over bit
// groups {b0,b1,b10,b11} / {b2..b5} / {b6..b9}, two smem exchanges.
// One CTA (256 threads) per row, 16 floats/thread — the best-measured
// config (many small independent CTAs; persistent/forced-occ variants all
// regressed). 768 L1 wavefronts/row (provable minimum); runs at the mixed
// R/W HBM ceiling (~6.9 TB/s effective).
//
// Issue-slot trims: butterflies are FFMA with ±1.0 immediate (rt_SMSP=1 on
// the fma pipe vs 2 for FADD), and the 1/64 scale is folded into the load
// (FMUL-imm, hidden under LDG latency) instead of the store tail.
//
// Smem: 4096 words (16 KB). GF(2) swizzle P(e) = e ^ (b6<<2) ^ (b10<<3) ^ (b11<<4)
// -> bank bits (b0, b1, b2^b6, b3^b10, b4^b11). Verified conflict-free:
//   W1 STS.128: 8-lane phases vary b2b3b4 -> distinct 4-bank groups
//   P2 scalar:  lanes vary b0,b1,b6,b10,b11 -> bank bijective
//   P3 scalar:  lanes vary b0..b4 -> bank bijective
// Exchange 1 is warp-local (chunk bits 5..7 equal the warp id for both the
// W1 writes and the pass-2 reads) -> __syncwarp; exchange 2 crosses the CTA
// -> __syncthreads. One full barrier per row.

#define FWHT_DIM 4096

__device__ __forceinline__ void h16(float (&v)[16]) {
#pragma unroll
    for (int h = 1; h < 16; h <<= 1) {
#pragma unroll
        for (int i = 0; i < 16; i++) {
            if (!(i & h)) {
                float a = v[i];
                float b = v[i + h];
                v[i]     = __fmaf_rn(b,  1.0f, a);   // FFMA-imm, rt 1
                v[i + h] = __fmaf_rn(b, -1.0f, a);
            }
        }
    }
}

__global__ __launch_bounds__(256)
void fwht4096_kernel(const float* __restrict__ x, float* __restrict__ y) {
    __shared__ float s[4096];   // 16 KB, swizzled

    const int t = threadIdx.x;                    // 0..255
    const size_t row = (size_t)blockIdx.x * FWHT_DIM;

    float v[16];

    // ---- Load: lane-contiguous LDG.128, prescaled by 1/64.
    //      v[4j+c] = element (j<<10)|(t<<2)|c: regs own {b0,b1,b10,b11}. ----
    {
        const float4* __restrict__ p = reinterpret_cast<const float4*>(x + row);
        const float sc = 0.015625f;   // 1/64 = 1/sqrt(4096), exact
#pragma unroll
        for (int j = 0; j < 4; j++) {
            float4 f = __ldcs(p + t + 256 * j);
            v[4 * j + 0] = f.x * sc;
            v[4 * j + 1] = f.y * sc;
            v[4 * j + 2] = f.z * sc;
            v[4 * j + 3] = f.w * sc;
        }
    }

    h16(v);   // H16 over {b0,b1,b10,b11}

    // ---- W1: 4x STS.128. Chunk c = t + 256j; swizzled chunk flips
    //      c0^=b6, c1^=b10, c2^=b11. ----
    {
        float4* s4 = reinterpret_cast<float4*>(s);
        const int tb = t ^ ((t >> 4) & 1);          // fold b6 into chunk bit 0
#pragma unroll
        for (int j = 0; j < 4; j++) {
            int cj = (tb ^ ((j & 1) << 1) ^ ((j & 2) << 1)) + 256 * j;
            s4[cj] = make_float4(v[4 * j], v[4 * j + 1],
                                 v[4 * j + 2], v[4 * j + 3]);
        }
    }
    __syncwarp();   // exchange 1 is warp-local by construction

    // ---- Pass 2: thread r owns b6=r&1, b0b1=(r>>1)&3, b10b11=(r>>3)&3,
    //      b7b8b9=r>>5; regs m = b2..b5.
    //      addr = base + ((4m) ^ sw), sw = (b6<<2)|(b10<<3)|(b11<<4). ----
    {
        const int base = ((t >> 1) & 3) | ((t & 1) << 6) | ((t >> 5) << 7)
                       | (((t >> 3) & 3) << 10);
        const int sw = ((t & 1) << 2) | (((t >> 3) & 1) << 3)
                     | (((t >> 4) & 1) << 4);
#pragma unroll
        for (int m = 0; m < 16; m++)
            v[m] = s[base + ((4 * m) ^ sw)];

        h16(v);   // H16 over {b2..b5}

#pragma unroll
        for (int m = 0; m < 16; m++)
            s[base + ((4 * m) ^ sw)] = v[m];
    }
    __syncthreads();   // exchange 2 crosses the whole CTA

    // ---- Pass 3: thread w owns b0..b5 = w&63, b10b11 = w>>6; regs k = b6..b9.
    //      addr = ((basew ^ swf) + 64k) ^ ((k&1)<<2). ----
    {
        const int basew = (t & 63) | ((t >> 6) << 10);
        const int swf = (((t >> 6) & 1) << 3) | (((t >> 7) & 1) << 4);
        const int pb = basew ^ swf;
#pragma unroll
        for (int k = 0; k < 16; k++)
            v[k] = s[(pb + 64 * k) ^ ((k & 1) << 2)];

        h16(v);   // H16 over {b6..b9}

        float* __restrict__ yr = y + row + basew;
#pragma unroll
        for (int k = 0; k < 16; k++)
            __stcs(yr + 64 * k, v[k]);   // warp-contiguous, 1 wf each
    }
}

extern "C" void kernel_launch(void* const* d_in, const int* in_sizes, int n_in,
                              void* d_out, int out_size) {
    (void)n_in; (void)out_size;
    const float* x = (const float*)d_in[0];
    float* y = (float*)d_out;
    const int rows = in_sizes[0] / FWHT_DIM;   // 16384
    fwht4096_kernel<<<rows, 256>>>(x, y);
}